// round 7
// baseline (speedup 1.0000x reference)
#include <cuda_runtime.h>
#include <cuda_fp16.h>
#include <cstdint>
#include <math.h>

// ===========================================================================
// TorchKAN via mma.sync (m16n8k16 fp16, fp32 accum) with fp16x3 split.
//   kan(X, W, A): S = X @ W^T ; out = sum_q A[:,q] * act_q(S)
// fp32 operand = fp16 hi + fp16 lo; S = Ah*Bh + Ah*Bl + Al*Bh (rel ~2^-22).
// R7: 512 threads (16 warps, 4x4 grid, 32x32 warp tiles) + cp.async 2-stage
// pipeline. Static smem only (36KB), no dynamic smem attr calls.
// ===========================================================================

#define B_SZ    32768
#define DIN_SZ  256
#define H_SZ    1024
#define DOUT_SZ 256

__device__ __half g_xh[B_SZ * DIN_SZ];
__device__ __half g_xl[B_SZ * DIN_SZ];
__device__ __half g_w1h[H_SZ * DIN_SZ];
__device__ __half g_w1l[H_SZ * DIN_SZ];
__device__ __half g_w2h[DOUT_SZ * H_SZ];
__device__ __half g_w2l[DOUT_SZ * H_SZ];
__device__ __half g_hh[(size_t)B_SZ * H_SZ];
__device__ __half g_hl[(size_t)B_SZ * H_SZ];

// ---------------- PTX helpers ----------------------------------------------
__device__ __forceinline__ uint32_t smem_u32(const void* p) {
    uint32_t a;
    asm("{ .reg .u64 t; cvta.to.shared.u64 t, %1; cvt.u32.u64 %0, t; }"
        : "=r"(a) : "l"(p));
    return a;
}

#define LDSM_X4(r, addr)                                                       \
    asm volatile("ldmatrix.sync.aligned.m8n8.x4.shared.b16 {%0,%1,%2,%3}, [%4];" \
                 : "=r"((r)[0]), "=r"((r)[1]), "=r"((r)[2]), "=r"((r)[3])      \
                 : "r"(addr))

#define MMA16816(d, a, b)                                                      \
    asm volatile("mma.sync.aligned.m16n8k16.row.col.f32.f16.f16.f32 "          \
                 "{%0,%1,%2,%3}, {%4,%5,%6,%7}, {%8,%9}, {%0,%1,%2,%3};"       \
                 : "+f"((d)[0]), "+f"((d)[1]), "+f"((d)[2]), "+f"((d)[3])      \
                 : "r"((a)[0]), "r"((a)[1]), "r"((a)[2]), "r"((a)[3]),         \
                   "r"((b)[0]), "r"((b)[1]))

#define CP_ASYNC16(smem, gmem)                                                 \
    asm volatile("cp.async.cg.shared.global [%0], [%1], 16;"                   \
                 :: "r"((uint32_t)(smem)), "l"(gmem))
#define CP_COMMIT()  asm volatile("cp.async.commit_group;" ::: "memory")
#define CP_WAIT0()   asm volatile("cp.async.wait_group 0;" ::: "memory")

// BK=16 tile: 128 rows x 16 halfs (two 16B chunks/row), 4KB per component.
// phys(row,c) = (row>>2)*128 + ((row&3) + 4*(c ^ ((row>>2)&1)))*16
// Conflict-free for both int4/cp.async stores and ldmatrix.x4 phases.
__device__ __forceinline__ uint32_t phys(uint32_t row, uint32_t c) {
    return (row >> 2) * 128u + (((row & 3u) + 4u * (c ^ ((row >> 2) & 1u))) << 4);
}

// ---------------- activation -----------------------------------------------
__device__ __forceinline__ float act_combine(float s, float a0, float a1,
                                             float a2, float a3, float a4, float a5) {
    float em  = __expf(-fabsf(s));
    float inv = 1.0f / (1.0f + em);
    float sig = (s >= 0.0f) ? inv : (1.0f - inv);
    float em2 = em * em;
    float th  = (1.0f - em2) / (1.0f + em2);
    th        = (s >= 0.0f) ? th : -th;
    float rl  = fmaxf(s, 0.0f);
    float lk  = (s > 0.0f) ? s : 0.01f * s;
    float sp  = rl + __logf(1.0f + em);
    float el  = (s > 0.0f) ? s : (em - 1.0f);
    float r;
    r = a0 * sig;
    r = fmaf(a1, th, r);
    r = fmaf(a2, rl, r);
    r = fmaf(a3, lk, r);
    r = fmaf(a4, sp, r);
    r = fmaf(a5, el, r);
    return r;
}

// ---------------- split kernel ---------------------------------------------
__global__ __launch_bounds__(256)
void split_kernel(const float4* __restrict__ in,
                  uint2* __restrict__ hi, uint2* __restrict__ lo, int n4) {
    int i = blockIdx.x * 256 + threadIdx.x;
    if (i >= n4) return;
    float4 v = __ldg(in + i);
    union { uint2 u; __half b[4]; } H, L;
    float f[4] = {v.x, v.y, v.z, v.w};
#pragma unroll
    for (int e = 0; e < 4; e++) {
        __half h = __float2half_rn(f[e]);
        H.b[e] = h;
        L.b[e] = __float2half_rn(f[e] - __half2float(h));
    }
    hi[i] = H.u;
    lo[i] = L.u;
}

// ---------------- main GEMM + activation -----------------------------------
// CTA 128x128, BK=16, 512 threads = 16 warps (4 M x 4 N), warp tile 32x32.
#define CSZ  4096          // one component tile bytes
#define STG  16384         // one stage (Ah, Al, Bh, Bl)

template<int OUT_SPLIT>
__global__ __launch_bounds__(512, 1)
void kan_tc(const __half* __restrict__ Ah, const __half* __restrict__ Al,
            const __half* __restrict__ Bh, const __half* __restrict__ Bl,
            const float* __restrict__ Ag,
            float* __restrict__ Of,
            __half* __restrict__ Oh, __half* __restrict__ Ol,
            int Kfull, int Ncols)
{
    __shared__ __align__(16)  float  s_coef[128 * 8];            // 4 KB
    __shared__ __align__(128) __half s_stage[2][4][2048];        // 32 KB

    const int tid  = threadIdx.x;
    const int wid  = tid >> 5;
    const int lane = tid & 31;
    const int wm   = wid >> 2;   // 0..3 (M)
    const int wn   = wid & 3;    // 0..3 (N)
    const int bm   = blockIdx.y * 128;
    const int bn   = blockIdx.x * 128;

    const uint32_t Sbase = smem_u32(&s_stage[0][0][0]);

    // loader: warps 0-7 fetch A hi/lo, warps 8-15 fetch B hi/lo.
    const int      grp  = tid >> 8;                 // 0 = A, 1 = B
    const uint32_t idx  = (uint32_t)(tid & 255);
    const uint32_t lrow = idx >> 1;                 // 0..127
    const uint32_t lc   = idx & 1;                  // chunk 0/1
    const uint32_t sw   = phys(lrow, lc);
    const __half*  gH   = (grp ? Bh : Ah) + (size_t)((grp ? bn : bm) + lrow) * Kfull + lc * 8;
    const __half*  gL   = (grp ? Bl : Al) + (size_t)((grp ? bn : bm) + lrow) * Kfull + lc * 8;
    const uint32_t dofH = (uint32_t)(grp * 2)     * CSZ + sw;
    const uint32_t dofL = (uint32_t)(grp * 2 + 1) * CSZ + sw;

    // coeffs (8-float stride for aligned vector reads)
    for (int i = tid; i < 128 * 6; i += 512) {
        int c = i / 6, q = i - c * 6;
        s_coef[c * 8 + q] = __ldg(Ag + (size_t)(bn + c) * 6 + q);
    }

    // ldmatrix per-lane byte offsets within a component tile
    const uint32_t rowA0 = (uint32_t)(wm * 32 + ((lane >> 3) & 1) * 8 + (lane & 7));
    const uint32_t cofA  = (uint32_t)(lane >> 4);
    const uint32_t offA0 = phys(rowA0,      cofA);
    const uint32_t offA1 = phys(rowA0 + 16, cofA);
    const uint32_t rowB  = (uint32_t)(wn * 32 + (lane >> 4) * 8 + (lane & 7));
    const uint32_t cofB  = (uint32_t)((lane >> 3) & 1);
    const uint32_t offB0 = phys(rowB,      cofB);
    const uint32_t offB1 = phys(rowB + 16, cofB);

    // prologue: stage 0 via cp.async
    CP_ASYNC16(Sbase + dofH, gH);
    CP_ASYNC16(Sbase + dofL, gL);
    CP_COMMIT();

    float acc[2][4][4];
#pragma unroll
    for (int mi = 0; mi < 2; mi++)
#pragma unroll
        for (int ni = 0; ni < 4; ni++)
#pragma unroll
            for (int e = 0; e < 4; e++) acc[mi][ni][e] = 0.0f;

    const int T = Kfull >> 4;   // BK = 16

    for (int t = 0; t < T; t++) {
        const uint32_t s = (uint32_t)(t & 1);

        CP_WAIT0();
        __syncthreads();        // stage s ready; all threads done with s^1

        if (t + 1 < T) {        // issue next stage before computing
            const int k0 = (t + 1) * 16;
            const uint32_t dst = Sbase + (s ^ 1u) * STG;
            CP_ASYNC16(dst + dofH, gH + k0);
            CP_ASYNC16(dst + dofL, gL + k0);
            CP_COMMIT();
        }

        const uint32_t stA = Sbase + s * STG;
        uint32_t ah[2][4], al[2][4], bh[4][2], bl[4][2];
        LDSM_X4(ah[0], stA + 0 * CSZ + offA0);
        LDSM_X4(ah[1], stA + 0 * CSZ + offA1);
        LDSM_X4(al[0], stA + 1 * CSZ + offA0);
        LDSM_X4(al[1], stA + 1 * CSZ + offA1);
        {
            uint32_t tmp[4];
            LDSM_X4(tmp, stA + 2 * CSZ + offB0);
            bh[0][0] = tmp[0]; bh[0][1] = tmp[1];
            bh[1][0] = tmp[2]; bh[1][1] = tmp[3];
            LDSM_X4(tmp, stA + 2 * CSZ + offB1);
            bh[2][0] = tmp[0]; bh[2][1] = tmp[1];
            bh[3][0] = tmp[2]; bh[3][1] = tmp[3];
            LDSM_X4(tmp, stA + 3 * CSZ + offB0);
            bl[0][0] = tmp[0]; bl[0][1] = tmp[1];
            bl[1][0] = tmp[2]; bl[1][1] = tmp[3];
            LDSM_X4(tmp, stA + 3 * CSZ + offB1);
            bl[2][0] = tmp[0]; bl[2][1] = tmp[1];
            bl[3][0] = tmp[2]; bl[3][1] = tmp[3];
        }
#pragma unroll
        for (int mi = 0; mi < 2; mi++)
#pragma unroll
            for (int ni = 0; ni < 4; ni++) {
                MMA16816(acc[mi][ni], ah[mi], bh[ni]);
                MMA16816(acc[mi][ni], ah[mi], bl[ni]);
                MMA16816(acc[mi][ni], al[mi], bh[ni]);
            }
        __syncthreads();        // done reading stage s before iter t+2 refills it
    }

    // ---- register-direct epilogue ----
    const int rr    = wm * 32 + (lane >> 2);
    const int cbase = wn * 32 + (lane & 3) * 2;

#pragma unroll
    for (int ni = 0; ni < 4; ni++) {
        const int c0 = cbase + ni * 8;
        const float* ap0 = &s_coef[(c0)     * 8];
        const float* ap1 = &s_coef[(c0 + 1) * 8];
        float4 u0 = *(const float4*)ap0; float2 u1 = *(const float2*)(ap0 + 4);
        float4 v0 = *(const float4*)ap1; float2 v1 = *(const float2*)(ap1 + 4);

#pragma unroll
        for (int mi = 0; mi < 2; mi++) {
#pragma unroll
            for (int rh = 0; rh < 2; rh++) {
                const float sa = acc[mi][ni][rh * 2 + 0];
                const float sb = acc[mi][ni][rh * 2 + 1];
                const float ra = act_combine(sa, u0.x, u0.y, u0.z, u0.w, u1.x, u1.y);
                const float rb = act_combine(sb, v0.x, v0.y, v0.z, v0.w, v1.x, v1.y);
                const int row = rr + mi * 16 + rh * 8;
                const size_t o = (size_t)(bm + row) * Ncols + bn + c0;
                if (OUT_SPLIT) {
                    __half ha = __float2half_rn(ra);
                    __half hb = __float2half_rn(rb);
                    __half la = __float2half_rn(ra - __half2float(ha));
                    __half lb = __float2half_rn(rb - __half2float(hb));
                    *(__half2*)(Oh + o) = __halves2half2(ha, hb);
                    *(__half2*)(Ol + o) = __halves2half2(la, lb);
                } else {
                    *(float2*)(Of + o) = make_float2(ra, rb);
                }
            }
        }
    }
}

// ---------------- host launcher --------------------------------------------
extern "C" void kernel_launch(void* const* d_in, const int* in_sizes, int n_in,
                              void* d_out, int out_size) {
    const float* x  = (const float*)d_in[0];
    const float* w1 = (const float*)d_in[1];
    const float* a1 = (const float*)d_in[2];
    const float* w2 = (const float*)d_in[3];
    const float* a2 = (const float*)d_in[4];
    float* out = (float*)d_out;

    __half *xh, *xl, *w1h, *w1l, *w2h, *w2l, *hh, *hl;
    cudaGetSymbolAddress((void**)&xh,  g_xh);
    cudaGetSymbolAddress((void**)&xl,  g_xl);
    cudaGetSymbolAddress((void**)&w1h, g_w1h);
    cudaGetSymbolAddress((void**)&w1l, g_w1l);
    cudaGetSymbolAddress((void**)&w2h, g_w2h);
    cudaGetSymbolAddress((void**)&w2l, g_w2l);
    cudaGetSymbolAddress((void**)&hh,  g_hh);
    cudaGetSymbolAddress((void**)&hl,  g_hl);

    const int nx4 = (B_SZ * DIN_SZ) / 4;
    const int nw4 = (H_SZ * DIN_SZ) / 4;
    split_kernel<<<nx4 / 256, 256>>>((const float4*)x,  (uint2*)xh,  (uint2*)xl,  nx4);
    split_kernel<<<nw4 / 256, 256>>>((const float4*)w1, (uint2*)w1h, (uint2*)w1l, nw4);
    split_kernel<<<nw4 / 256, 256>>>((const float4*)w2, (uint2*)w2h, (uint2*)w2l, nw4);

    // layer 1: [32768,256] x [1024,256]^T -> hidden fp16 hi/lo
    kan_tc<1><<<dim3(H_SZ / 128, B_SZ / 128), 512>>>(
        xh, xl, w1h, w1l, a1, nullptr, hh, hl, DIN_SZ, H_SZ);

    // layer 2: [32768,1024] x [256,1024]^T -> out fp32
    kan_tc<0><<<dim3(DOUT_SZ / 128, B_SZ / 128), 512>>>(
        hh, hl, w2h, w2l, a2, out, nullptr, nullptr, H_SZ, DOUT_SZ);
}